// round 4
// baseline (speedup 1.0000x reference)
#include <cuda_runtime.h>
#include <math.h>

#define NB 4
#define NT 512
#define DMODEL 769
#define DINNER 1538
#define DSTATE 64
#define DTRANK 49
#define BT (NB*NT)            // 2048 rows
#define XPROJ_N 177           // DT_RANK + 2*D_STATE

// ---------------- scratch (static device globals; no allocation) ----------------
__device__ float g_xT [NB*64*NT];         // x transposed (B,64,T)
__device__ float g_h0 [NB*128*NT];        // pointconv out (B,128,T)
__device__ float g_h2 [NB*768*NT];        // conv stack out (B,768,T)
__device__ float g_h  [BT*DMODEL];        // residual stream (B,T,769)
__device__ float g_un [BT*DMODEL];        // normalized buffer
__device__ float g_xz [BT*2*DINNER];      // in_proj out (B,T,3076)
__device__ float g_xin[BT*DINNER];        // post dw-conv silu
__device__ float g_dbc[BT*XPROJ_N];       // x_proj out
__device__ float g_dt [BT*DINNER];        // softplus(dt)
__device__ float g_y  [BT*DINNER];        // scan out

__device__ __forceinline__ float silu_f(float v){ return v / (1.f + __expf(-v)); }

// ---------------- x (B,T,65) -> g_xT (B,64,T) ----------------
__global__ void k_xt(const float* __restrict__ x){
    __shared__ float tile[32][33];
    int b  = blockIdx.z;
    int t0 = blockIdx.x*32, c0 = blockIdx.y*32;
    int tx = threadIdx.x, ty = threadIdx.y;
    tile[ty][tx] = x[(b*NT + t0 + ty)*65 + c0 + tx];
    __syncthreads();
    g_xT[(b*64 + c0 + ty)*NT + t0 + tx] = tile[tx][ty];
}

// ---------------- front: pointwise conv (64->128) + silu (coalesced) ------------
__global__ void k_pointconv(const float* __restrict__ pw,
                            const float* __restrict__ pb){
    int idx = blockIdx.x*256 + threadIdx.x;          // 4*128*512 threads
    int t = idx & 511;
    int c = (idx >> 9) & 127;
    int b = idx >> 16;
    const float* xr = g_xT + b*64*NT + t;            // stride NT over i, lane-coalesced
    const float* wr = pw + c*64;                     // broadcast within warp
    float acc = pb[c];
#pragma unroll
    for (int i = 0; i < 64; i++) acc += xr[i*NT]*wr[i];
    g_h0[(b*128 + c)*NT + t] = silu_f(acc);
}

// ---------------- front: KS-tap conv over time (128 -> 256 per branch) + silu ----
template<int KS>
__global__ void k_conv(const float* __restrict__ w,
                       const float* __restrict__ bias,
                       int ocBase){
    __shared__ float ws[128*KS];
    __shared__ float xs[8][544];
    const int tid = threadIdx.x;                 // 128 threads, 4 t's each
    const int ocl = blockIdx.x & 255;
    const int b   = blockIdx.x >> 8;
    const int pad = (KS - 1)/2;

    const float* wp = w + ocl*128*KS;
    for (int i = tid; i < 128*KS; i += 128) ws[i] = wp[i];

    float acc0 = bias[ocl], acc1 = acc0, acc2 = acc0, acc3 = acc0;

    for (int icb = 0; icb < 128; icb += 8){
        __syncthreads();
#pragma unroll
        for (int r = 0; r < 8; r++){
            const float* hrow = g_h0 + (b*128 + icb + r)*NT;
            for (int j = tid; j < 538; j += 128){
                int tt = j - 13;
                xs[r][j] = (tt >= 0 && tt < NT) ? hrow[tt] : 0.f;
            }
        }
        __syncthreads();
#pragma unroll
        for (int r = 0; r < 8; r++){
            float xv[KS+3];
            const int base = tid*4 + 13 - pad;
#pragma unroll
            for (int q = 0; q < KS+3; q++) xv[q] = xs[r][base + q];
            const float* wr = ws + (icb + r)*KS;
#pragma unroll
            for (int k = 0; k < KS; k++){
                float wk = wr[k];
                acc0 += wk*xv[k];   acc1 += wk*xv[k+1];
                acc2 += wk*xv[k+2]; acc3 += wk*xv[k+3];
            }
        }
    }
    float* o = g_h2 + (b*768 + ocBase + ocl)*NT + tid*4;
    o[0] = silu_f(acc0); o[1] = silu_f(acc1);
    o[2] = silu_f(acc2); o[3] = silu_f(acc3);
}

// ---------------- (B,C,T) -> (B,T,769) transpose ----------------
__global__ void k_transpose(){
    __shared__ float tile[32][33];
    int b  = blockIdx.z;
    int t0 = blockIdx.x*32, c0 = blockIdx.y*32;
    int tx = threadIdx.x, ty = threadIdx.y;
    tile[ty][tx] = g_h2[(b*768 + c0 + ty)*NT + t0 + tx];
    __syncthreads();
    g_h[(b*NT + t0 + ty)*DMODEL + c0 + tx] = tile[tx][ty];
}

__global__ void k_pe(const float* __restrict__ x){
    int i = blockIdx.x*256 + threadIdx.x;
    if (i >= BT) return;
    g_h[i*DMODEL + 768] = x[i*65 + 64];
}

// ---------------- rmsnorm / layernorm (row per block) ----------------
__global__ void k_rmsnorm(const float* __restrict__ w){
    int m = blockIdx.x, tid = threadIdx.x;
    const float* row = g_h + m*DMODEL;
    float s = 0.f;
    for (int k = tid; k < DMODEL; k += 256){ float v = row[k]; s += v*v; }
#pragma unroll
    for (int o = 16; o > 0; o >>= 1) s += __shfl_xor_sync(0xffffffffu, s, o);
    __shared__ float red[8];
    if ((tid & 31) == 0) red[tid >> 5] = s;
    __syncthreads();
    s = red[0]+red[1]+red[2]+red[3]+red[4]+red[5]+red[6]+red[7];
    float sc = rsqrtf(s/769.f + 1e-6f);
    float* o = g_un + m*DMODEL;
    for (int k = tid; k < DMODEL; k += 256) o[k] = row[k]*sc*w[k];
}

__global__ void k_layernorm(const float* __restrict__ w, const float* __restrict__ bb){
    int m = blockIdx.x, tid = threadIdx.x;
    const float* row = g_h + m*DMODEL;
    float s1 = 0.f, s2 = 0.f;
    for (int k = tid; k < DMODEL; k += 256){ float v = row[k]; s1 += v; s2 += v*v; }
#pragma unroll
    for (int o = 16; o > 0; o >>= 1){
        s1 += __shfl_xor_sync(0xffffffffu, s1, o);
        s2 += __shfl_xor_sync(0xffffffffu, s2, o);
    }
    __shared__ float r1[8], r2[8];
    if ((tid & 31) == 0){ r1[tid >> 5] = s1; r2[tid >> 5] = s2; }
    __syncthreads();
    s1 = 0.f; s2 = 0.f;
#pragma unroll
    for (int i = 0; i < 8; i++){ s1 += r1[i]; s2 += r2[i]; }
    float mean = s1/769.f;
    float var  = s2/769.f - mean*mean;
    float istd = rsqrtf(var + 1e-5f);
    float* o = g_un + m*DMODEL;
    for (int k = tid; k < DMODEL; k += 256)
        o[k] = (row[k] - mean)*istd*w[k] + bb[k];
}

// ---------------- SGEMM 128x128: C = A(MxK) * W(NxK)^T (big grids only) ---------
__global__ void __launch_bounds__(256, 2)
k_sgemm128(const float* __restrict__ A, int lda,
           const float* __restrict__ W, int ldw,
           float* __restrict__ C, int ldc,
           int M, int N, int K){
    __shared__ __align__(16) float As[2][8][128];
    __shared__ __align__(16) float Ws[2][8][128];

    const int tid = threadIdx.x;
    const int m0 = blockIdx.y*128, n0 = blockIdx.x*128;
    const int tx = tid & 15, ty = tid >> 4;

    const int lr = tid >> 1;            // 0..127
    const int lc = (tid & 1) * 4;       // 0 or 4
    const int gmA = m0 + lr;
    const int gnW = n0 + lr;
    const bool okA = (gmA < M);
    const bool okW = (gnW < N);
    const float* Ap = A + (size_t)gmA*lda;
    const float* Wp = W + (size_t)gnW*ldw;

    float acc[8][8];
#pragma unroll
    for (int i = 0; i < 8; i++)
#pragma unroll
        for (int j = 0; j < 8; j++) acc[i][j] = 0.f;

    const int nk = (K + 7) >> 3;
    float ra[4], rw[4];

    {
#pragma unroll
        for (int q = 0; q < 4; q++){
            int gk = lc + q;
            ra[q] = (okA && gk < K) ? Ap[gk] : 0.f;
            rw[q] = (okW && gk < K) ? Wp[gk] : 0.f;
        }
#pragma unroll
        for (int q = 0; q < 4; q++){
            As[0][lc + q][lr] = ra[q];
            Ws[0][lc + q][lr] = rw[q];
        }
    }
    __syncthreads();

    int buf = 0;
    for (int kt = 0; kt < nk; kt++){
        if (kt + 1 < nk){
            int k0 = (kt + 1) << 3;
#pragma unroll
            for (int q = 0; q < 4; q++){
                int gk = k0 + lc + q;
                ra[q] = (okA && gk < K) ? Ap[gk] : 0.f;
                rw[q] = (okW && gk < K) ? Wp[gk] : 0.f;
            }
        }

#pragma unroll
        for (int kk = 0; kk < 8; kk++){
            float a[8], b[8];
            *(float4*)(a)     = *(const float4*)&As[buf][kk][ty*8];
            *(float4*)(a + 4) = *(const float4*)&As[buf][kk][ty*8 + 4];
            *(float4*)(b)     = *(const float4*)&Ws[buf][kk][tx*8];
            *(float4*)(b + 4) = *(const float4*)&Ws[buf][kk][tx*8 + 4];
#pragma unroll
            for (int i = 0; i < 8; i++)
#pragma unroll
                for (int j = 0; j < 8; j++) acc[i][j] += a[i]*b[j];
        }

        if (kt + 1 < nk){
            int nb = buf ^ 1;
#pragma unroll
            for (int q = 0; q < 4; q++){
                As[nb][lc + q][lr] = ra[q];
                Ws[nb][lc + q][lr] = rw[q];
            }
            __syncthreads();
            buf = nb;
        }
    }

#pragma unroll
    for (int i = 0; i < 8; i++){
        int gm = m0 + ty*8 + i;
        if (gm >= M) continue;
        float* crow = C + (size_t)gm*ldc;
#pragma unroll
        for (int j = 0; j < 8; j++){
            int gn = n0 + tx*8 + j;
            if (gn < N) crow[gn] = acc[i][j];
        }
    }
}

// ---------------- SGEMM 64x64: C = epi(A(MxK) * W(NxK)^T) (small grids) ---------
// epi: 0 = none, 1 = bias + softplus, 2 = C += acc (residual)
__global__ void k_sgemm64(const float* __restrict__ A, int lda,
                          const float* __restrict__ W, int ldw,
                          float* __restrict__ C, int ldc,
                          int M, int N, int K,
                          const float* __restrict__ bias, int epi){
    __shared__ __align__(16) float As[16][68];
    __shared__ __align__(16) float Ws[16][68];
    const int tid = threadIdx.x;
    const int m0 = blockIdx.y*64, n0 = blockIdx.x*64;
    const int tx = tid & 15, ty = tid >> 4;

    float acc[4][4];
#pragma unroll
    for (int i = 0; i < 4; i++)
#pragma unroll
        for (int j = 0; j < 4; j++) acc[i][j] = 0.f;

    for (int k0 = 0; k0 < K; k0 += 16){
        for (int i = tid; i < 1024; i += 256){
            int mm = i >> 4, kk = i & 15;
            int gk = k0 + kk;
            int gm = m0 + mm;
            As[kk][mm] = (gm < M && gk < K) ? A[gm*lda + gk] : 0.f;
            int gn = n0 + mm;
            Ws[kk][mm] = (gn < N && gk < K) ? W[gn*ldw + gk] : 0.f;
        }
        __syncthreads();
#pragma unroll
        for (int kk = 0; kk < 16; kk++){
            float4 a4 = *(const float4*)&As[kk][ty*4];
            float4 w4 = *(const float4*)&Ws[kk][tx*4];
            float av[4] = {a4.x, a4.y, a4.z, a4.w};
            float wv[4] = {w4.x, w4.y, w4.z, w4.w};
#pragma unroll
            for (int i = 0; i < 4; i++)
#pragma unroll
                for (int j = 0; j < 4; j++) acc[i][j] += av[i]*wv[j];
        }
        __syncthreads();
    }

#pragma unroll
    for (int i = 0; i < 4; i++){
        int gm = m0 + ty*4 + i;
        if (gm >= M) continue;
#pragma unroll
        for (int j = 0; j < 4; j++){
            int gn = n0 + tx*4 + j;
            if (gn >= N) continue;
            float v = acc[i][j];
            float* cp = &C[gm*ldc + gn];
            if (epi == 1){
                v += bias[gn];
                v = fmaxf(v, 0.f) + log1pf(expf(-fabsf(v)));   // stable softplus
                *cp = v;
            } else if (epi == 2){
                *cp = *cp + v;
            } else {
                *cp = v;
            }
        }
    }
}

// ---------------- depthwise causal conv (k=4) + silu ----------------
__global__ void k_dwconv(const float* __restrict__ cw, const float* __restrict__ cb){
    int idx = blockIdx.x*256 + threadIdx.x;           // BT*DINNER threads
    int d  = idx % DINNER;
    int bt = idx / DINNER;
    int t  = bt & 511;
    float acc = cb[d];
#pragma unroll
    for (int k = 0; k < 4; k++){
        int tt = t - 3 + k;
        if (tt >= 0) acc += cw[d*4 + k] * g_xz[(bt - 3 + k)*2*DINNER + d];
    }
    g_xin[bt*DINNER + d] = silu_f(acc);
}

// ---------------- selective scan: warp per (b,d), 2 states/lane ----------------
__global__ void k_scan(const float* __restrict__ Alog, const float* __restrict__ Dv){
    int w    = blockIdx.x*4 + (threadIdx.x >> 5);     // 6152 warps
    int lane = threadIdx.x & 31;
    int b = w & 3;
    int d = w >> 2;

    float A1 = -__expf(Alog[d*64 + lane]);
    float A2 = -__expf(Alog[d*64 + lane + 32]);
    float Dd = Dv[d];
    float h1 = 0.f, h2 = 0.f;

    int r = b*NT;
    for (int t = 0; t < NT; t++, r++){
        float dtv = g_dt [r*DINNER + d];
        float uv  = g_xin[r*DINNER + d];
        const float* q = g_dbc + r*XPROJ_N;
        float B1 = q[49  + lane], B2 = q[81  + lane];
        float C1 = q[113 + lane], C2 = q[145 + lane];
        float du = dtv*uv;
        h1 = __expf(dtv*A1)*h1 + du*B1;
        h2 = __expf(dtv*A2)*h2 + du*B2;
        float p = h1*C1 + h2*C2;
#pragma unroll
        for (int o = 16; o > 0; o >>= 1) p += __shfl_xor_sync(0xffffffffu, p, o);
        if (lane == 0){
            float zv = g_xz[r*2*DINNER + DINNER + d];
            g_y[r*DINNER + d] = (p + uv*Dd) * silu_f(zv);
        }
    }
}

// ---------------- classifier: warp per (row, class) ----------------
__global__ void k_classifier(const float* __restrict__ ow,
                             const float* __restrict__ ob,
                             float* __restrict__ out){
    int m = blockIdx.x;
    int wid  = threadIdx.x >> 5;      // 10 warps / block
    int lane = threadIdx.x & 31;
    const float* u  = g_un + m*DMODEL;
    const float* wr = ow + wid*DMODEL;
    float s = 0.f;
    for (int k = lane; k < DMODEL; k += 32) s += u[k]*wr[k];
#pragma unroll
    for (int o = 16; o > 0; o >>= 1) s += __shfl_xor_sync(0xffffffffu, s, o);
    if (lane == 0) out[m*10 + wid] = s + ob[wid];
}

// ---------------- orchestration ----------------
extern "C" void kernel_launch(void* const* d_in, const int* in_sizes, int n_in,
                              void* d_out, int out_size){
    const float* x    = (const float*)d_in[0];
    const float* pw   = (const float*)d_in[1];
    const float* pb   = (const float*)d_in[2];
    const float* c1w  = (const float*)d_in[3];
    const float* c1b  = (const float*)d_in[4];
    const float* c2w  = (const float*)d_in[5];
    const float* c2b  = (const float*)d_in[6];
    const float* c3w  = (const float*)d_in[7];
    const float* c3b  = (const float*)d_in[8];
    const float* lnw  = (const float*)d_in[9];
    const float* lnb  = (const float*)d_in[10];
    const float* ow   = (const float*)d_in[11];
    const float* ob   = (const float*)d_in[12];
    const float* rmsw = (const float*)d_in[13];
    const float* inw  = (const float*)d_in[14];
    const float* dww  = (const float*)d_in[15];
    const float* dwb  = (const float*)d_in[16];
    const float* xpw  = (const float*)d_in[17];
    const float* dtw  = (const float*)d_in[18];
    const float* dtb  = (const float*)d_in[19];
    const float* alog = (const float*)d_in[20];
    const float* dsk  = (const float*)d_in[21];
    const float* opw  = (const float*)d_in[22];

    float *p_un, *p_xz, *p_xin, *p_dbc, *p_dt, *p_y, *p_h;
    cudaGetSymbolAddress((void**)&p_un,  g_un);
    cudaGetSymbolAddress((void**)&p_xz,  g_xz);
    cudaGetSymbolAddress((void**)&p_xin, g_xin);
    cudaGetSymbolAddress((void**)&p_dbc, g_dbc);
    cudaGetSymbolAddress((void**)&p_dt,  g_dt);
    cudaGetSymbolAddress((void**)&p_y,   g_y);
    cudaGetSymbolAddress((void**)&p_h,   g_h);

    k_xt<<<dim3(16, 2, 4), dim3(32, 32)>>>(x);
    k_pointconv<<<1024, 256>>>(pw, pb);
    k_conv<3> <<<1024, 128>>>(c1w, c1b, 0);
    k_conv<9> <<<1024, 128>>>(c2w, c2b, 256);
    k_conv<27><<<1024, 128>>>(c3w, c3b, 512);
    k_transpose<<<dim3(16, 24, 4), dim3(32, 32)>>>();
    k_pe<<<8, 256>>>(x);

    for (int l = 0; l < 2; l++){
        k_rmsnorm<<<2048, 256>>>(rmsw + l*DMODEL);
        // xz = un @ Wi^T       (2048 x 3076, K=769)  -> 128x128 tile, 400 blocks
        k_sgemm128<<<dim3(25, 16), 256>>>(p_un, DMODEL,
                                          inw + (size_t)l*2*DINNER*DMODEL, DMODEL,
                                          p_xz, 2*DINNER,
                                          BT, 2*DINNER, DMODEL);
        k_dwconv<<<12304, 256>>>(dww + l*DINNER*4, dwb + l*DINNER);
        // dbc = xin @ Wx^T     (2048 x 177, K=1538)  -> 64x64, 96 blocks
        k_sgemm64<<<dim3(3, 32), 256>>>(p_xin, DINNER,
                                        xpw + (size_t)l*XPROJ_N*DINNER, DINNER,
                                        p_dbc, XPROJ_N,
                                        BT, XPROJ_N, DINNER, nullptr, 0);
        // dt = softplus(dbc[:, :49] @ Wdt^T + bdt)   (2048 x 1538, K=49)
        k_sgemm64<<<dim3(25, 32), 256>>>(p_dbc, XPROJ_N,
                                         dtw + (size_t)l*DINNER*DTRANK, DTRANK,
                                         p_dt, DINNER,
                                         BT, DINNER, DTRANK, dtb + l*DINNER, 1);
        k_scan<<<1538, 128>>>(alog + (size_t)l*DINNER*DSTATE, dsk + l*DINNER);
        // h += y @ Wo^T        (2048 x 769, K=1538)  -> 64x64, 416 blocks
        k_sgemm64<<<dim3(13, 32), 256>>>(p_y, DINNER,
                                         opw + (size_t)l*DMODEL*DINNER, DINNER,
                                         p_h, DMODEL,
                                         BT, DMODEL, DINNER, nullptr, 2);
    }

    k_layernorm<<<2048, 256>>>(lnw, lnb);
    k_classifier<<<2048, 320>>>(ow, ob, (float*)d_out);
}

// round 5
// speedup vs baseline: 1.1267x; 1.1267x over previous
#include <cuda_runtime.h>
#include <math.h>

#define NB 4
#define NT 512
#define DMODEL 769
#define DINNER 1538
#define DSTATE 64
#define DTRANK 49
#define BT (NB*NT)            // 2048 rows
#define XPROJ_N 177           // DT_RANK + 2*D_STATE

// ---------------- scratch (static device globals; no allocation) ----------------
__device__ float g_xT [NB*64*NT];         // x transposed (B,64,T)
__device__ float g_h0 [NB*128*NT];        // pointconv out (B,128,T)
__device__ float g_h2 [NB*768*NT];        // conv stack out (B,768,T)
__device__ float g_h  [BT*DMODEL];        // residual stream (B,T,769)
__device__ float g_un [BT*DMODEL];        // normalized buffer
__device__ float g_xz [BT*2*DINNER];      // in_proj out (B,T,3076)
__device__ float g_xin[BT*DINNER];        // post dw-conv silu
__device__ float g_dbc[BT*XPROJ_N];       // x_proj out
__device__ float g_dt [BT*DINNER];        // softplus(dt)
__device__ float g_y  [BT*DINNER];        // scan out

__device__ __forceinline__ float silu_f(float v){ return v / (1.f + __expf(-v)); }

// ---------------- x (B,T,65) -> g_xT (B,64,T) ----------------
__global__ void k_xt(const float* __restrict__ x){
    __shared__ float tile[32][33];
    int b  = blockIdx.z;
    int t0 = blockIdx.x*32, c0 = blockIdx.y*32;
    int tx = threadIdx.x, ty = threadIdx.y;
    tile[ty][tx] = x[(b*NT + t0 + ty)*65 + c0 + tx];
    __syncthreads();
    g_xT[(b*64 + c0 + ty)*NT + t0 + tx] = tile[tx][ty];
}

// ---------------- front: pointwise conv (64->128) + silu (coalesced) ------------
__global__ void k_pointconv(const float* __restrict__ pw,
                            const float* __restrict__ pb){
    int idx = blockIdx.x*256 + threadIdx.x;          // 4*128*512 threads
    int t = idx & 511;
    int c = (idx >> 9) & 127;
    int b = idx >> 16;
    const float* xr = g_xT + b*64*NT + t;            // stride NT over i, lane-coalesced
    const float* wr = pw + c*64;                     // broadcast within warp
    float acc = pb[c];
#pragma unroll
    for (int i = 0; i < 64; i++) acc += xr[i*NT]*wr[i];
    g_h0[(b*128 + c)*NT + t] = silu_f(acc);
}

// ---- front: KS-tap conv over time (128 -> 256 per branch) + silu ----
// staging loop: EXACT R1 version (flat loop; measured issue=66%)
template<int KS>
__global__ void k_conv(const float* __restrict__ w,
                       const float* __restrict__ bias,
                       int ocBase){
    __shared__ float ws[128*KS];
    __shared__ float xs[8][544];
    const int tid = threadIdx.x;                 // 128 threads, 4 t's each
    const int ocl = blockIdx.x & 255;
    const int b   = blockIdx.x >> 8;
    const int pad = (KS - 1)/2;

    const float* wp = w + ocl*128*KS;
    for (int i = tid; i < 128*KS; i += 128) ws[i] = wp[i];

    float acc0 = bias[ocl], acc1 = acc0, acc2 = acc0, acc3 = acc0;

    for (int icb = 0; icb < 128; icb += 8){
        __syncthreads();
        for (int i = tid; i < 8*538; i += 128){
            int r = i / 538, j = i - r*538;
            int tt = j - 13;
            const float* hrow = g_h0 + (b*128 + icb + r)*NT;
            xs[r][j] = (tt >= 0 && tt < NT) ? hrow[tt] : 0.f;
        }
        __syncthreads();
#pragma unroll
        for (int r = 0; r < 8; r++){
            float xv[KS+3];
            const int base = tid*4 + 13 - pad;
#pragma unroll
            for (int q = 0; q < KS+3; q++) xv[q] = xs[r][base + q];
            const float* wr = ws + (icb + r)*KS;
#pragma unroll
            for (int k = 0; k < KS; k++){
                float wk = wr[k];
                acc0 += wk*xv[k];   acc1 += wk*xv[k+1];
                acc2 += wk*xv[k+2]; acc3 += wk*xv[k+3];
            }
        }
    }
    float* o = g_h2 + (b*768 + ocBase + ocl)*NT + tid*4;
    o[0] = silu_f(acc0); o[1] = silu_f(acc1);
    o[2] = silu_f(acc2); o[3] = silu_f(acc3);
}

// ---------------- (B,C,T) -> (B,T,769) transpose ----------------
__global__ void k_transpose(){
    __shared__ float tile[32][33];
    int b  = blockIdx.z;
    int t0 = blockIdx.x*32, c0 = blockIdx.y*32;
    int tx = threadIdx.x, ty = threadIdx.y;
    tile[ty][tx] = g_h2[(b*768 + c0 + ty)*NT + t0 + tx];
    __syncthreads();
    g_h[(b*NT + t0 + ty)*DMODEL + c0 + tx] = tile[tx][ty];
}

__global__ void k_pe(const float* __restrict__ x){
    int i = blockIdx.x*256 + threadIdx.x;
    if (i >= BT) return;
    g_h[i*DMODEL + 768] = x[i*65 + 64];
}

// ---------------- rmsnorm / layernorm (row per block) ----------------
__global__ void k_rmsnorm(const float* __restrict__ w){
    int m = blockIdx.x, tid = threadIdx.x;
    const float* row = g_h + m*DMODEL;
    float s = 0.f;
    for (int k = tid; k < DMODEL; k += 256){ float v = row[k]; s += v*v; }
#pragma unroll
    for (int o = 16; o > 0; o >>= 1) s += __shfl_xor_sync(0xffffffffu, s, o);
    __shared__ float red[8];
    if ((tid & 31) == 0) red[tid >> 5] = s;
    __syncthreads();
    s = red[0]+red[1]+red[2]+red[3]+red[4]+red[5]+red[6]+red[7];
    float sc = rsqrtf(s/769.f + 1e-6f);
    float* o = g_un + m*DMODEL;
    for (int k = tid; k < DMODEL; k += 256) o[k] = row[k]*sc*w[k];
}

__global__ void k_layernorm(const float* __restrict__ w, const float* __restrict__ bb){
    int m = blockIdx.x, tid = threadIdx.x;
    const float* row = g_h + m*DMODEL;
    float s1 = 0.f, s2 = 0.f;
    for (int k = tid; k < DMODEL; k += 256){ float v = row[k]; s1 += v; s2 += v*v; }
#pragma unroll
    for (int o = 16; o > 0; o >>= 1){
        s1 += __shfl_xor_sync(0xffffffffu, s1, o);
        s2 += __shfl_xor_sync(0xffffffffu, s2, o);
    }
    __shared__ float r1[8], r2[8];
    if ((tid & 31) == 0){ r1[tid >> 5] = s1; r2[tid >> 5] = s2; }
    __syncthreads();
    s1 = 0.f; s2 = 0.f;
#pragma unroll
    for (int i = 0; i < 8; i++){ s1 += r1[i]; s2 += r2[i]; }
    float mean = s1/769.f;
    float var  = s2/769.f - mean*mean;
    float istd = rsqrtf(var + 1e-5f);
    float* o = g_un + m*DMODEL;
    for (int k = tid; k < DMODEL; k += 256)
        o[k] = (row[k] - mean)*istd*w[k] + bb[k];
}

// ---------------- SGEMM 128x128: C = A(MxK) * W(NxK)^T (big grids only) ---------
__global__ void __launch_bounds__(256, 2)
k_sgemm128(const float* __restrict__ A, int lda,
           const float* __restrict__ W, int ldw,
           float* __restrict__ C, int ldc,
           int M, int N, int K){
    __shared__ __align__(16) float As[2][8][128];
    __shared__ __align__(16) float Ws[2][8][128];

    const int tid = threadIdx.x;
    const int m0 = blockIdx.y*128, n0 = blockIdx.x*128;
    const int tx = tid & 15, ty = tid >> 4;

    const int lr = tid >> 1;            // 0..127
    const int lc = (tid & 1) * 4;       // 0 or 4
    const int gmA = m0 + lr;
    const int gnW = n0 + lr;
    const bool okA = (gmA < M);
    const bool okW = (gnW < N);
    const float* Ap = A + (size_t)gmA*lda;
    const float* Wp = W + (size_t)gnW*ldw;

    float acc[8][8];
#pragma unroll
    for (int i = 0; i < 8; i++)
#pragma unroll
        for (int j = 0; j < 8; j++) acc[i][j] = 0.f;

    const int nk = (K + 7) >> 3;
    float ra[4], rw[4];

    {
#pragma unroll
        for (int q = 0; q < 4; q++){
            int gk = lc + q;
            ra[q] = (okA && gk < K) ? Ap[gk] : 0.f;
            rw[q] = (okW && gk < K) ? Wp[gk] : 0.f;
        }
#pragma unroll
        for (int q = 0; q < 4; q++){
            As[0][lc + q][lr] = ra[q];
            Ws[0][lc + q][lr] = rw[q];
        }
    }
    __syncthreads();

    int buf = 0;
    for (int kt = 0; kt < nk; kt++){
        if (kt + 1 < nk){
            int k0 = (kt + 1) << 3;
#pragma unroll
            for (int q = 0; q < 4; q++){
                int gk = k0 + lc + q;
                ra[q] = (okA && gk < K) ? Ap[gk] : 0.f;
                rw[q] = (okW && gk < K) ? Wp[gk] : 0.f;
            }
        }

#pragma unroll
        for (int kk = 0; kk < 8; kk++){
            float a[8], b[8];
            *(float4*)(a)     = *(const float4*)&As[buf][kk][ty*8];
            *(float4*)(a + 4) = *(const float4*)&As[buf][kk][ty*8 + 4];
            *(float4*)(b)     = *(const float4*)&Ws[buf][kk][tx*8];
            *(float4*)(b + 4) = *(const float4*)&Ws[buf][kk][tx*8 + 4];
#pragma unroll
            for (int i = 0; i < 8; i++)
#pragma unroll
                for (int j = 0; j < 8; j++) acc[i][j] += a[i]*b[j];
        }

        if (kt + 1 < nk){
            int nb = buf ^ 1;
#pragma unroll
            for (int q = 0; q < 4; q++){
                As[nb][lc + q][lr] = ra[q];
                Ws[nb][lc + q][lr] = rw[q];
            }
            __syncthreads();
            buf = nb;
        }
    }

#pragma unroll
    for (int i = 0; i < 8; i++){
        int gm = m0 + ty*8 + i;
        if (gm >= M) continue;
        float* crow = C + (size_t)gm*ldc;
#pragma unroll
        for (int j = 0; j < 8; j++){
            int gn = n0 + tx*8 + j;
            if (gn < N) crow[gn] = acc[i][j];
        }
    }
}

// ---------------- SGEMM 64x64: C = epi(A(MxK) * W(NxK)^T) (small grids) ---------
// epi: 0 = none, 1 = bias + softplus, 2 = C += acc (residual)
__global__ void k_sgemm64(const float* __restrict__ A, int lda,
                          const float* __restrict__ W, int ldw,
                          float* __restrict__ C, int ldc,
                          int M, int N, int K,
                          const float* __restrict__ bias, int epi){
    __shared__ __align__(16) float As[16][68];
    __shared__ __align__(16) float Ws[16][68];
    const int tid = threadIdx.x;
    const int m0 = blockIdx.y*64, n0 = blockIdx.x*64;
    const int tx = tid & 15, ty = tid >> 4;

    float acc[4][4];
#pragma unroll
    for (int i = 0; i < 4; i++)
#pragma unroll
        for (int j = 0; j < 4; j++) acc[i][j] = 0.f;

    for (int k0 = 0; k0 < K; k0 += 16){
        for (int i = tid; i < 1024; i += 256){
            int mm = i >> 4, kk = i & 15;
            int gk = k0 + kk;
            int gm = m0 + mm;
            As[kk][mm] = (gm < M && gk < K) ? A[gm*lda + gk] : 0.f;
            int gn = n0 + mm;
            Ws[kk][mm] = (gn < N && gk < K) ? W[gn*ldw + gk] : 0.f;
        }
        __syncthreads();
#pragma unroll
        for (int kk = 0; kk < 16; kk++){
            float4 a4 = *(const float4*)&As[kk][ty*4];
            float4 w4 = *(const float4*)&Ws[kk][tx*4];
            float av[4] = {a4.x, a4.y, a4.z, a4.w};
            float wv[4] = {w4.x, w4.y, w4.z, w4.w};
#pragma unroll
            for (int i = 0; i < 4; i++)
#pragma unroll
                for (int j = 0; j < 4; j++) acc[i][j] += av[i]*wv[j];
        }
        __syncthreads();
    }

#pragma unroll
    for (int i = 0; i < 4; i++){
        int gm = m0 + ty*4 + i;
        if (gm >= M) continue;
#pragma unroll
        for (int j = 0; j < 4; j++){
            int gn = n0 + tx*4 + j;
            if (gn >= N) continue;
            float v = acc[i][j];
            float* cp = &C[gm*ldc + gn];
            if (epi == 1){
                v += bias[gn];
                v = fmaxf(v, 0.f) + log1pf(expf(-fabsf(v)));   // stable softplus
                *cp = v;
            } else if (epi == 2){
                *cp = *cp + v;
            } else {
                *cp = v;
            }
        }
    }
}

// ---------------- depthwise causal conv (k=4) + silu ----------------
__global__ void k_dwconv(const float* __restrict__ cw, const float* __restrict__ cb){
    int idx = blockIdx.x*256 + threadIdx.x;           // BT*DINNER threads
    int d  = idx % DINNER;
    int bt = idx / DINNER;
    int t  = bt & 511;
    float acc = cb[d];
#pragma unroll
    for (int k = 0; k < 4; k++){
        int tt = t - 3 + k;
        if (tt >= 0) acc += cw[d*4 + k] * g_xz[(bt - 3 + k)*2*DINNER + d];
    }
    g_xin[bt*DINNER + d] = silu_f(acc);
}

// ---------------- selective scan: warp per (b,d), 2 states/lane ----------------
__global__ void k_scan(const float* __restrict__ Alog, const float* __restrict__ Dv){
    int w    = blockIdx.x*4 + (threadIdx.x >> 5);     // 6152 warps
    int lane = threadIdx.x & 31;
    int b = w & 3;
    int d = w >> 2;

    float A1 = -__expf(Alog[d*64 + lane]);
    float A2 = -__expf(Alog[d*64 + lane + 32]);
    float Dd = Dv[d];
    float h1 = 0.f, h2 = 0.f;

    int r = b*NT;
    for (int t = 0; t < NT; t++, r++){
        float dtv = g_dt [r*DINNER + d];
        float uv  = g_xin[r*DINNER + d];
        const float* q = g_dbc + r*XPROJ_N;
        float B1 = q[49  + lane], B2 = q[81  + lane];
        float C1 = q[113 + lane], C2 = q[145 + lane];
        float du = dtv*uv;
        h1 = __expf(dtv*A1)*h1 + du*B1;
        h2 = __expf(dtv*A2)*h2 + du*B2;
        float p = h1*C1 + h2*C2;
#pragma unroll
        for (int o = 16; o > 0; o >>= 1) p += __shfl_xor_sync(0xffffffffu, p, o);
        if (lane == 0){
            float zv = g_xz[r*2*DINNER + DINNER + d];
            g_y[r*DINNER + d] = (p + uv*Dd) * silu_f(zv);
        }
    }
}

// ---------------- classifier: warp per (row, class) ----------------
__global__ void k_classifier(const float* __restrict__ ow,
                             const float* __restrict__ ob,
                             float* __restrict__ out){
    int m = blockIdx.x;
    int wid  = threadIdx.x >> 5;      // 10 warps / block
    int lane = threadIdx.x & 31;
    const float* u  = g_un + m*DMODEL;
    const float* wr = ow + wid*DMODEL;
    float s = 0.f;
    for (int k = lane; k < DMODEL; k += 32) s += u[k]*wr[k];
#pragma unroll
    for (int o = 16; o > 0; o >>= 1) s += __shfl_xor_sync(0xffffffffu, s, o);
    if (lane == 0) out[m*10 + wid] = s + ob[wid];
}

// ---------------- orchestration ----------------
extern "C" void kernel_launch(void* const* d_in, const int* in_sizes, int n_in,
                              void* d_out, int out_size){
    const float* x    = (const float*)d_in[0];
    const float* pw   = (const float*)d_in[1];
    const float* pb   = (const float*)d_in[2];
    const float* c1w  = (const float*)d_in[3];
    const float* c1b  = (const float*)d_in[4];
    const float* c2w  = (const float*)d_in[5];
    const float* c2b  = (const float*)d_in[6];
    const float* c3w  = (const float*)d_in[7];
    const float* c3b  = (const float*)d_in[8];
    const float* lnw  = (const float*)d_in[9];
    const float* lnb  = (const float*)d_in[10];
    const float* ow   = (const float*)d_in[11];
    const float* ob   = (const float*)d_in[12];
    const float* rmsw = (const float*)d_in[13];
    const float* inw  = (const float*)d_in[14];
    const float* dww  = (const float*)d_in[15];
    const float* dwb  = (const float*)d_in[16];
    const float* xpw  = (const float*)d_in[17];
    const float* dtw  = (const float*)d_in[18];
    const float* dtb  = (const float*)d_in[19];
    const float* alog = (const float*)d_in[20];
    const float* dsk  = (const float*)d_in[21];
    const float* opw  = (const float*)d_in[22];

    float *p_un, *p_xz, *p_xin, *p_dbc, *p_dt, *p_y, *p_h;
    cudaGetSymbolAddress((void**)&p_un,  g_un);
    cudaGetSymbolAddress((void**)&p_xz,  g_xz);
    cudaGetSymbolAddress((void**)&p_xin, g_xin);
    cudaGetSymbolAddress((void**)&p_dbc, g_dbc);
    cudaGetSymbolAddress((void**)&p_dt,  g_dt);
    cudaGetSymbolAddress((void**)&p_y,   g_y);
    cudaGetSymbolAddress((void**)&p_h,   g_h);

    k_xt<<<dim3(16, 2, 4), dim3(32, 32)>>>(x);
    k_pointconv<<<1024, 256>>>(pw, pb);
    k_conv<3> <<<1024, 128>>>(c1w, c1b, 0);
    k_conv<9> <<<1024, 128>>>(c2w, c2b, 256);
    k_conv<27><<<1024, 128>>>(c3w, c3b, 512);
    k_transpose<<<dim3(16, 24, 4), dim3(32, 32)>>>();
    k_pe<<<8, 256>>>(x);

    for (int l = 0; l < 2; l++){
        k_rmsnorm<<<2048, 256>>>(rmsw + l*DMODEL);
        // xz = un @ Wi^T       (2048 x 3076, K=769)  -> 128x128 tile, 400 blocks
        k_sgemm128<<<dim3(25, 16), 256>>>(p_un, DMODEL,
                                          inw + (size_t)l*2*DINNER*DMODEL, DMODEL,
                                          p_xz, 2*DINNER,
                                          BT, 2*DINNER, DMODEL);
        k_dwconv<<<12304, 256>>>(dww + l*DINNER*4, dwb + l*DINNER);
        // dbc = xin @ Wx^T     (2048 x 177, K=1538)  -> 64x64, 96 blocks
        k_sgemm64<<<dim3(3, 32), 256>>>(p_xin, DINNER,
                                        xpw + (size_t)l*XPROJ_N*DINNER, DINNER,
                                        p_dbc, XPROJ_N,
                                        BT, XPROJ_N, DINNER, nullptr, 0);
        // dt = softplus(dbc[:, :49] @ Wdt^T + bdt)   (2048 x 1538, K=49)
        k_sgemm64<<<dim3(25, 32), 256>>>(p_dbc, XPROJ_N,
                                         dtw + (size_t)l*DINNER*DTRANK, DTRANK,
                                         p_dt, DINNER,
                                         BT, DINNER, DTRANK, dtb + l*DINNER, 1);
        k_scan<<<1538, 128>>>(alog + (size_t)l*DINNER*DSTATE, dsk + l*DINNER);
        // h += y @ Wo^T        (2048 x 769, K=1538)  -> 64x64, 416 blocks
        k_sgemm64<<<dim3(13, 32), 256>>>(p_y, DINNER,
                                         opw + (size_t)l*DMODEL*DINNER, DINNER,
                                         p_h, DMODEL,
                                         BT, DMODEL, DINNER, nullptr, 2);
    }

    k_layernorm<<<2048, 256>>>(lnw, lnb);
    k_classifier<<<2048, 320>>>(ow, ob, (float*)d_out);
}